// round 5
// baseline (speedup 1.0000x reference)
#include <cuda_runtime.h>

#define SEQ 262144
#define IN  100
#define HID 40

// scratch (allocation-free rule: __device__ globals). g_A padded so the
// phase-2 prefetch ring (depth 8) can read past the end unguarded.
__device__ float g_A[SEQ * HID + 8 * HID + 64];   // a_i = Wx @ x_i
__device__ float g_T[SEQ * HID];                  // t_i trace for phase 3

typedef unsigned long long u64;

__device__ __forceinline__ u64 pack2(float lo, float hi) {
    u64 r; asm("mov.b64 %0, {%1,%2};" : "=l"(r) : "f"(lo), "f"(hi)); return r;
}
__device__ __forceinline__ void unpack2(u64 v, float& lo, float& hi) {
    asm("mov.b64 {%0,%1}, %2;" : "=f"(lo), "=f"(hi) : "l"(v));
}
__device__ __forceinline__ u64 fma2(u64 a, u64 b, u64 c) {
    u64 d; asm("fma.rn.f32x2 %0, %1, %2, %3;" : "=l"(d) : "l"(a), "l"(b), "l"(c)); return d;
}
__device__ __forceinline__ u64 add2(u64 a, u64 b) {
    u64 d; asm("add.rn.f32x2 %0, %1, %2;" : "=l"(d) : "l"(a), "l"(b)); return d;
}
__device__ __forceinline__ float hadd2(u64 v) {
    float lo, hi; unpack2(v, lo, hi); return lo + hi;
}
__device__ __forceinline__ float tanh_approx(float x) {
    float r; asm("tanh.approx.f32 %0, %1;" : "=f"(r) : "f"(x)); return r;
}

// ============================================================================
// Phase 1: g_A[i][j] = sum_k Wx[j][k] * s[i][k]   (fully parallel)
// ============================================================================
__global__ void __launch_bounds__(32) phase1_kernel(
    const float* __restrict__ s, const float* __restrict__ Wx)
{
    __shared__ __align__(16) float wx[HID * IN];   // 16000 B
    __shared__ u64 xs[IN / 2][32];                 // 12800 B

    const int lane = threadIdx.x;

    const float4* wsrc = (const float4*)Wx;
    float4* wdst = (float4*)wx;
    for (int t = lane; t < (HID * IN) / 4; t += 32) wdst[t] = wsrc[t];

    const int i = blockIdx.x * 32 + lane;
    const float4* xr = (const float4*)(s + (size_t)i * IN);
#pragma unroll
    for (int c = 0; c < IN / 4; ++c) {
        float4 v = xr[c];
        xs[2 * c][lane]     = pack2(v.x, v.y);
        xs[2 * c + 1][lane] = pack2(v.z, v.w);
    }
    __syncthreads();

    float* Ao = g_A + (size_t)i * HID;
#pragma unroll 1
    for (int j = 0; j < HID; ++j) {
        const u64* wrow = (const u64*)(wx + j * IN);
        u64 acc[4] = {0, 0, 0, 0};
#pragma unroll
        for (int k = 0; k < IN / 2; ++k) {
            acc[k & 3] = fma2(wrow[k], xs[k][lane], acc[k & 3]);
        }
        Ao[j] = hadd2(add2(add2(acc[0], acc[1]), add2(acc[2], acc[3])));
    }
}

// ============================================================================
// Phase 2: serial recurrence. EXACTLY 40 threads (warp0 full + 8 lanes of
// warp1), thread j owns output row j. No dead lanes -> shared-crossbar
// traffic for the t broadcast drops from 10240B to 6400B per step.
// a folded into chain head (depth-8 prefetch ring). STG after the barrier.
// ============================================================================
__global__ void __launch_bounds__(40, 1) phase2_kernel(
    const float* __restrict__ init, const float* __restrict__ Wh,
    float* __restrict__ tfinal)
{
    __shared__ __align__(16) float tsh[2][48];   // rows 40..47 padding

    const int j = threadIdx.x;                   // 0..39, all active

    // preload Wh row j into registers
    u64 wh[HID / 2];
    const float2* wr = (const float2*)(Wh + j * HID);
#pragma unroll
    for (int p = 0; p < HID / 2; ++p) {
        float2 w = wr[p];
        wh[p] = pack2(w.x, w.y);
    }

    tsh[0][j] = init[j];
    tsh[1][j] = 0.0f;
    if (j < 8) { tsh[0][40 + j] = 0.0f; tsh[1][40 + j] = 0.0f; }

    // prefetch ring for a, depth 8 (g_A padded; no bounds checks)
    const float* ap = g_A + j;
    float a[8];
#pragma unroll
    for (int d = 0; d < 8; ++d) a[d] = ap[d * HID];
    ap += 8 * HID;

    __syncthreads();

    float outv = tsh[0][j];
    float* gT = g_T + j;

#pragma unroll 2
    for (int i = 0; i < SEQ; ++i) {
        const int rb   = i & 1;
        const int slot = i & 7;
        const ulonglong2* tb = (const ulonglong2*)tsh[rb];

        // ---- batched t loads: 10x LDS.128, no consumers in between ----
        ulonglong2 p0 = tb[0], p1 = tb[1], p2 = tb[2], p3 = tb[3], p4 = tb[4];
        ulonglong2 p5 = tb[5], p6 = tb[6], p7 = tb[7], p8 = tb[8], p9 = tb[9];

        // prefetch a_{i+8} (independent; 8-step lead covers DRAM latency)
        float anew = ap[0];
        ap += HID;

        // ---- 4 independent fma2 chains, depth 5; a at the head ----
        u64 acc0 = fma2(wh[0],  p0.x, pack2(a[slot], 0.0f));
        u64 acc1 = fma2(wh[1],  p0.y, 0ull);
        u64 acc2 = fma2(wh[2],  p1.x, 0ull);
        u64 acc3 = fma2(wh[3],  p1.y, 0ull);
        acc0 = fma2(wh[4],  p2.x, acc0);
        acc1 = fma2(wh[5],  p2.y, acc1);
        acc2 = fma2(wh[6],  p3.x, acc2);
        acc3 = fma2(wh[7],  p3.y, acc3);
        acc0 = fma2(wh[8],  p4.x, acc0);
        acc1 = fma2(wh[9],  p4.y, acc1);
        acc2 = fma2(wh[10], p5.x, acc2);
        acc3 = fma2(wh[11], p5.y, acc3);
        acc0 = fma2(wh[12], p6.x, acc0);
        acc1 = fma2(wh[13], p6.y, acc1);
        acc2 = fma2(wh[14], p7.x, acc2);
        acc3 = fma2(wh[15], p7.y, acc3);
        acc0 = fma2(wh[16], p8.x, acc0);
        acc1 = fma2(wh[17], p8.y, acc1);
        acc2 = fma2(wh[18], p9.x, acc2);
        acc3 = fma2(wh[19], p9.y, acc3);
        a[slot] = anew;

        float v = hadd2(add2(add2(acc0, acc1), add2(acc2, acc3)));

        outv = tanh_approx(v);

        tsh[rb ^ 1][j] = outv;        // STS, then arrive at the barrier

        __syncthreads();

        gT[(size_t)i * HID] = outv;   // STG off the sync-critical path
    }

    tfinal[j] = outv;
}

// ============================================================================
// Phase 3: y_i = softmax(Wy @ t_i)  (fully parallel, one warp per timestep)
// ============================================================================
#define WYPAD 42
__global__ void __launch_bounds__(256) phase3_kernel(
    const float* __restrict__ Wy, float* __restrict__ ys)
{
    __shared__ __align__(8) float wy[IN * WYPAD];

    const int tid = threadIdx.x;
    for (int t = tid; t < IN * HID; t += 256) {
        int jrow = t / HID, kr = t % HID;
        wy[jrow * WYPAD + kr] = Wy[t];
    }
    __syncthreads();

    const int lane = tid & 31;
    const int warp = blockIdx.x * 8 + (tid >> 5);
    const int nwarp = gridDim.x * 8;

    for (int i = warp; i < SEQ; i += nwarp) {
        const ulonglong2* tp = (const ulonglong2*)(g_T + (size_t)i * HID);
        u64 t2[HID / 2];
#pragma unroll
        for (int p = 0; p < 10; ++p) {
            ulonglong2 v = tp[p];
            t2[2 * p]     = v.x;
            t2[2 * p + 1] = v.y;
        }

        float z[4];
#pragma unroll
        for (int o = 0; o < 4; ++o) {
            const int jj = lane + 32 * o;
            if (jj < IN) {
                const u64* wrow = (const u64*)(wy + jj * WYPAD);
                u64 acc[4] = {0, 0, 0, 0};
#pragma unroll
                for (int p = 0; p < HID / 2; ++p)
                    acc[p & 3] = fma2(wrow[p], t2[p], acc[p & 3]);
                z[o] = hadd2(add2(add2(acc[0], acc[1]), add2(acc[2], acc[3])));
            } else {
                z[o] = -1e30f;
            }
        }

        float m = fmaxf(fmaxf(z[0], z[1]), fmaxf(z[2], z[3]));
#pragma unroll
        for (int off = 16; off; off >>= 1)
            m = fmaxf(m, __shfl_xor_sync(0xffffffffu, m, off));

        float e[4];
        float ssum = 0.0f;
#pragma unroll
        for (int o = 0; o < 4; ++o) {
            const int jj = lane + 32 * o;
            e[o] = (jj < IN) ? __expf(z[o] - m) : 0.0f;
            ssum += e[o];
        }
#pragma unroll
        for (int off = 16; off; off >>= 1)
            ssum += __shfl_xor_sync(0xffffffffu, ssum, off);

        const float r = __fdividef(1.0f, ssum);
        float* yo = ys + (size_t)i * IN;
#pragma unroll
        for (int o = 0; o < 4; ++o) {
            const int jj = lane + 32 * o;
            if (jj < IN) yo[jj] = e[o] * r;
        }
    }
}

// ============================================================================
// inputs (metadata order): s[SEQ*IN] f32, initialState[HID] f32,
//                          Wx[HID*IN] f32, Wh[HID*HID] f32, Wy[IN*HID] f32
// output: t_final[HID] then ys[SEQ*IN], float32
// ============================================================================
extern "C" void kernel_launch(void* const* d_in, const int* in_sizes, int n_in,
                              void* d_out, int out_size)
{
    const float* s    = (const float*)d_in[0];
    const float* init = (const float*)d_in[1];
    const float* Wx   = (const float*)d_in[2];
    const float* Wh   = (const float*)d_in[3];
    const float* Wy   = (const float*)d_in[4];
    float* out = (float*)d_out;

    phase1_kernel<<<SEQ / 32, 32>>>(s, Wx);
    phase2_kernel<<<1, 40>>>(init, Wh, out);          // writes out[0..39] + g_T
    phase3_kernel<<<2048, 256>>>(Wy, out + HID);      // writes ys
}

// round 6
// speedup vs baseline: 2.0687x; 2.0687x over previous
#include <cuda_runtime.h>

#define SEQ 262144
#define IN  100
#define HID 40
#define ASTRIDE (SEQ + 8)   // padded row stride for transposed A

// scratch (allocation-free rule: __device__ globals)
__device__ float g_AT[HID * ASTRIDE];   // a transposed: g_AT[j*ASTRIDE + i]
__device__ float g_T[SEQ * HID];        // t_i trace for phase 3

typedef unsigned long long u64;

__device__ __forceinline__ u64 pack2(float lo, float hi) {
    u64 r; asm("mov.b64 %0, {%1,%2};" : "=l"(r) : "f"(lo), "f"(hi)); return r;
}
__device__ __forceinline__ void unpack2(u64 v, float& lo, float& hi) {
    asm("mov.b64 {%0,%1}, %2;" : "=f"(lo), "=f"(hi) : "l"(v));
}
__device__ __forceinline__ u64 fma2(u64 a, u64 b, u64 c) {
    u64 d; asm("fma.rn.f32x2 %0, %1, %2, %3;" : "=l"(d) : "l"(a), "l"(b), "l"(c)); return d;
}
__device__ __forceinline__ u64 add2(u64 a, u64 b) {
    u64 d; asm("add.rn.f32x2 %0, %1, %2;" : "=l"(d) : "l"(a), "l"(b)); return d;
}
__device__ __forceinline__ float hadd2(u64 v) {
    float lo, hi; unpack2(v, lo, hi); return lo + hi;
}
__device__ __forceinline__ float tanh_approx(float x) {
    float r; asm("tanh.approx.f32 %0, %1;" : "=f"(r) : "f"(x)); return r;
}

// ============================================================================
// Phase 1: g_AT[j][i] = sum_k Wx[j][k] * s[i][k]   (fully parallel)
// lane = timestep within a 32-step tile; writes are 128B-coalesced per row j.
// ============================================================================
__global__ void __launch_bounds__(32) phase1_kernel(
    const float* __restrict__ s, const float* __restrict__ Wx)
{
    __shared__ __align__(16) float wx[HID * IN];   // 16000 B
    __shared__ u64 xs[IN / 2][32];                 // 12800 B

    const int lane = threadIdx.x;

    const float4* wsrc = (const float4*)Wx;
    float4* wdst = (float4*)wx;
    for (int t = lane; t < (HID * IN) / 4; t += 32) wdst[t] = wsrc[t];

    const int i = blockIdx.x * 32 + lane;
    const float4* xr = (const float4*)(s + (size_t)i * IN);
#pragma unroll
    for (int c = 0; c < IN / 4; ++c) {
        float4 v = xr[c];
        xs[2 * c][lane]     = pack2(v.x, v.y);
        xs[2 * c + 1][lane] = pack2(v.z, v.w);
    }
    __syncthreads();

#pragma unroll 1
    for (int j = 0; j < HID; ++j) {
        const u64* wrow = (const u64*)(wx + j * IN);
        u64 acc[4] = {0, 0, 0, 0};
#pragma unroll
        for (int k = 0; k < IN / 2; ++k) {
            acc[k & 3] = fma2(wrow[k], xs[k][lane], acc[k & 3]);
        }
        g_AT[j * ASTRIDE + i] = hadd2(add2(add2(acc[0], acc[1]), add2(acc[2], acc[3])));
    }
}

// ============================================================================
// Phase 2: serial recurrence. 64 threads (2 warps), thread j < 40 owns row j.
// a values come from TRANSPOSED layout: 2x LDG.128 per 8 steps into named
// float4 registers -> ring is fully static, NO local memory, no dynamic idx.
// t double-buffered in shared; batched LDS.128; single-MUFU tanh.
// ============================================================================
__global__ void __launch_bounds__(64, 1) phase2_kernel(
    const float* __restrict__ init, const float* __restrict__ Wh,
    float* __restrict__ tfinal)
{
    __shared__ __align__(16) float tsh[2][64];

    const int j  = threadIdx.x;
    const int jr = (j < HID) ? j : 0;          // clamp for OOB-safe loads
    const bool act = (j < HID);

    // preload Wh row jr into registers
    u64 wh[HID / 2];
    const float2* wr = (const float2*)(Wh + jr * HID);
#pragma unroll
    for (int p = 0; p < HID / 2; ++p) {
        float2 w = wr[p];
        wh[p] = pack2(w.x, w.y);
    }

    tsh[0][j] = act ? init[j] : 0.0f;
    tsh[1][j] = 0.0f;

    // current + next 8-step a blocks in named registers
    const float4* arow = (const float4*)(g_AT + (size_t)jr * ASTRIDE);
    float4 c0 = arow[0], c1 = arow[1];     // a for steps 0..7
    arow += 2;

    __syncthreads();

    float outv = tsh[0][j];
    float* gT = g_T + jr;

#pragma unroll 1
    for (int ib = 0; ib < SEQ; ib += 8) {
        // prefetch a for steps ib+8 .. ib+15 (padded row; safe at the end)
        float4 n0 = arow[0], n1 = arow[1];
        arow += 2;

#pragma unroll
        for (int u = 0; u < 8; ++u) {
            const int rb = u & 1;   // tsh[0] holds even-step inputs (ib is even)
            const ulonglong2* tb = (const ulonglong2*)tsh[rb];

            // static selection of this step's a (all compile-time)
            float av = (u == 0) ? c0.x : (u == 1) ? c0.y : (u == 2) ? c0.z :
                       (u == 3) ? c0.w : (u == 4) ? c1.x : (u == 5) ? c1.y :
                       (u == 6) ? c1.z : c1.w;

            // ---- batched t loads: 10x LDS.128 ----
            ulonglong2 p0 = tb[0], p1 = tb[1], p2 = tb[2], p3 = tb[3], p4 = tb[4];
            ulonglong2 p5 = tb[5], p6 = tb[6], p7 = tb[7], p8 = tb[8], p9 = tb[9];

            // ---- 4 independent fma2 chains, depth 5; a at the head ----
            u64 acc0 = fma2(wh[0],  p0.x, pack2(av, 0.0f));
            u64 acc1 = fma2(wh[1],  p0.y, 0ull);
            u64 acc2 = fma2(wh[2],  p1.x, 0ull);
            u64 acc3 = fma2(wh[3],  p1.y, 0ull);
            acc0 = fma2(wh[4],  p2.x, acc0);
            acc1 = fma2(wh[5],  p2.y, acc1);
            acc2 = fma2(wh[6],  p3.x, acc2);
            acc3 = fma2(wh[7],  p3.y, acc3);
            acc0 = fma2(wh[8],  p4.x, acc0);
            acc1 = fma2(wh[9],  p4.y, acc1);
            acc2 = fma2(wh[10], p5.x, acc2);
            acc3 = fma2(wh[11], p5.y, acc3);
            acc0 = fma2(wh[12], p6.x, acc0);
            acc1 = fma2(wh[13], p6.y, acc1);
            acc2 = fma2(wh[14], p7.x, acc2);
            acc3 = fma2(wh[15], p7.y, acc3);
            acc0 = fma2(wh[16], p8.x, acc0);
            acc1 = fma2(wh[17], p8.y, acc1);
            acc2 = fma2(wh[18], p9.x, acc2);
            acc3 = fma2(wh[19], p9.y, acc3);

            float v = hadd2(add2(add2(acc0, acc1), add2(acc2, acc3)));

            outv = tanh_approx(v);

            tsh[rb ^ 1][j] = outv;        // STS, then arrive at the barrier
            __syncthreads();

            if (act) gT[(size_t)(ib + u) * HID] = outv;  // off the sync path
        }

        c0 = n0; c1 = n1;
    }

    if (act) tfinal[j] = outv;
}

// ============================================================================
// Phase 3: y_i = softmax(Wy @ t_i)  (fully parallel, one warp per timestep)
// ============================================================================
#define WYPAD 42
__global__ void __launch_bounds__(256) phase3_kernel(
    const float* __restrict__ Wy, float* __restrict__ ys)
{
    __shared__ __align__(8) float wy[IN * WYPAD];

    const int tid = threadIdx.x;
    for (int t = tid; t < IN * HID; t += 256) {
        int jrow = t / HID, kr = t % HID;
        wy[jrow * WYPAD + kr] = Wy[t];
    }
    __syncthreads();

    const int lane = tid & 31;
    const int warp = blockIdx.x * 8 + (tid >> 5);
    const int nwarp = gridDim.x * 8;

    for (int i = warp; i < SEQ; i += nwarp) {
        const ulonglong2* tp = (const ulonglong2*)(g_T + (size_t)i * HID);
        u64 t2[HID / 2];
#pragma unroll
        for (int p = 0; p < 10; ++p) {
            ulonglong2 v = tp[p];
            t2[2 * p]     = v.x;
            t2[2 * p + 1] = v.y;
        }

        float z[4];
#pragma unroll
        for (int o = 0; o < 4; ++o) {
            const int jj = lane + 32 * o;
            if (jj < IN) {
                const u64* wrow = (const u64*)(wy + jj * WYPAD);
                u64 acc[4] = {0, 0, 0, 0};
#pragma unroll
                for (int p = 0; p < HID / 2; ++p)
                    acc[p & 3] = fma2(wrow[p], t2[p], acc[p & 3]);
                z[o] = hadd2(add2(add2(acc[0], acc[1]), add2(acc[2], acc[3])));
            } else {
                z[o] = -1e30f;
            }
        }

        float m = fmaxf(fmaxf(z[0], z[1]), fmaxf(z[2], z[3]));
#pragma unroll
        for (int off = 16; off; off >>= 1)
            m = fmaxf(m, __shfl_xor_sync(0xffffffffu, m, off));

        float e[4];
        float ssum = 0.0f;
#pragma unroll
        for (int o = 0; o < 4; ++o) {
            const int jj = lane + 32 * o;
            e[o] = (jj < IN) ? __expf(z[o] - m) : 0.0f;
            ssum += e[o];
        }
#pragma unroll
        for (int off = 16; off; off >>= 1)
            ssum += __shfl_xor_sync(0xffffffffu, ssum, off);

        const float r = __fdividef(1.0f, ssum);
        float* yo = ys + (size_t)i * IN;
#pragma unroll
        for (int o = 0; o < 4; ++o) {
            const int jj = lane + 32 * o;
            if (jj < IN) yo[jj] = e[o] * r;
        }
    }
}

// ============================================================================
// inputs (metadata order): s[SEQ*IN] f32, initialState[HID] f32,
//                          Wx[HID*IN] f32, Wh[HID*HID] f32, Wy[IN*HID] f32
// output: t_final[HID] then ys[SEQ*IN], float32
// ============================================================================
extern "C" void kernel_launch(void* const* d_in, const int* in_sizes, int n_in,
                              void* d_out, int out_size)
{
    const float* s    = (const float*)d_in[0];
    const float* init = (const float*)d_in[1];
    const float* Wx   = (const float*)d_in[2];
    const float* Wh   = (const float*)d_in[3];
    const float* Wy   = (const float*)d_in[4];
    float* out = (float*)d_out;

    phase1_kernel<<<SEQ / 32, 32>>>(s, Wx);
    phase2_kernel<<<1, 64>>>(init, Wh, out);          // writes out[0..39] + g_T
    phase3_kernel<<<2048, 256>>>(Wy, out + HID);      // writes ys
}